// round 5
// baseline (speedup 1.0000x reference)
#include <cuda_runtime.h>
#include <cuda_bf16.h>

// BundleAdjustment, round 5: full pose table EXACT in shared memory.
//  - quat float4[8192] (128 KB) + translation planar x/y/z float[8192] (96 KB) = 224 KB smem
//  - pose gathers become divergent LDS (cheap) instead of divergent LDG wavefronts
//  - patch gather stays 1x LDG.128 from precomputed local-cartesian table
//  - 1 block/SM x 1024 threads, persistent grid-stride, 2 edges/thread

#define R_MIN   0.5f
#define R_MAX   30.0f
#define BINS    512.0f
#define BEAMS   512.0f
#define FOV_H   2.0943951f

#define E_NUM   4194304
#define P_NUM   8192

// Scratch (device globals -- allocation-free per harness rules)
__device__ float4 g_patch_cart[E_NUM];    // 64 MB: local cartesian (x, y, z, 0)
__device__ float4 g_quat[P_NUM];          // 128 KB: (qx, qy, qz, qw) exact
__device__ float  g_tx[P_NUM];            // 32 KB each: translation planar
__device__ float  g_ty[P_NUM];
__device__ float  g_tz[P_NUM];

// ---------------- Fused prepass ----------------
__global__ __launch_bounds__(256) void prepass(
    const float* __restrict__ poses,
    const float* __restrict__ init_poses,
    const float* __restrict__ patch_coords,  // float2 per patch
    const float* __restrict__ elev,
    const float* __restrict__ init_elev,
    float*       __restrict__ out_pose,      // out + 2E
    float*       __restrict__ out_elev,      // out + 2E + P7
    int E, int P7)
{
    const int tid    = blockIdx.x * blockDim.x + threadIdx.x;
    const int stride = gridDim.x * blockDim.x;

    // pose residual (first 57344 threads)
    if (tid < P7) out_pose[tid] = poses[tid] - init_poses[tid];

    // pose packing (exact)
    if (tid < P_NUM) {
        const float* p = poses + 7 * tid;
        g_tx[tid]   = p[0];
        g_ty[tid]   = p[1];
        g_tz[tid]   = p[2];
        g_quat[tid] = make_float4(p[3], p[4], p[5], p[6]);
    }

    // patch pack + elev residual, 2 patches per iteration (float4 loads)
    const int H = E >> 1;  // E is even
    #pragma unroll 2
    for (int i = tid; i < H; i += stride) {
        const float4 pc2 = __ldg(((const float4*)patch_coords) + i);  // (r0,th0,r1,th1)
        const float2 ph2 = __ldg(((const float2*)elev) + i);
        const float2 ie2 = __ldg(((const float2*)init_elev) + i);
        ((float2*)out_elev)[i] = make_float2(ph2.x - ie2.x, ph2.y - ie2.y);

        float st, ct, sph, cph;
        __sincosf(pc2.y, &st, &ct);
        __sincosf(ph2.x, &sph, &cph);
        float rcp = pc2.x * cph;
        g_patch_cart[2 * i] = make_float4(rcp * ct, rcp * st, pc2.x * sph, 0.0f);

        __sincosf(pc2.w, &st, &ct);
        __sincosf(ph2.y, &sph, &cph);
        rcp = pc2.z * cph;
        g_patch_cart[2 * i + 1] = make_float4(rcp * ct, rcp * st, pc2.z * sph, 0.0f);
    }
}

// ---------------- Main: reprojection residual ----------------
struct SmemTables {
    const float4* q;
    const float*  tx;
    const float*  ty;
    const float*  tz;
};

__device__ __forceinline__ float2 project_one(const SmemTables& S,
                                              int p, int s, int t, float2 tg)
{
    const float4 pk = __ldg(&g_patch_cart[p]);   // local cartesian
    float vx = pk.x, vy = pk.y, vz = pk.z;

    // src pose: rotate + translate (all from smem, exact)
    {
        const float4 q = S.q[s];
        const float qx = q.x, qy = q.y, qz = q.z, qw = q.w;
        const float tx = 2.0f * (qy * vz - qz * vy);
        const float ty = 2.0f * (qz * vx - qx * vz);
        const float tz = 2.0f * (qx * vy - qy * vx);
        const float rx = vx + qw * tx + (qy * tz - qz * ty);
        const float ry = vy + qw * ty + (qz * tx - qx * tz);
        const float rz = vz + qw * tz + (qx * ty - qy * tx);
        vx = rx + S.tx[s]; vy = ry + S.ty[s]; vz = rz + S.tz[s];
    }

    // tgt pose: translate + inverse rotate
    vx -= S.tx[t]; vy -= S.ty[t]; vz -= S.tz[t];
    float lx, ly, lz;
    {
        const float4 q = S.q[t];
        const float qx = -q.x, qy = -q.y, qz = -q.z, qw = q.w;
        const float tx = 2.0f * (qy * vz - qz * vy);
        const float ty = 2.0f * (qz * vx - qx * vz);
        const float tz = 2.0f * (qx * vy - qy * vx);
        lx = vx + qw * tx + (qy * tz - qz * ty);
        ly = vy + qw * ty + (qz * tx - qx * tz);
        lz = vz + qw * tz + (qx * ty - qy * tx);
    }

    const float r3 = sqrtf(lx * lx + ly * ly + lz * lz);
    const float th = atan2f(ly, lx);

    float2 res;
    res.x = (r3 - tg.x) * (BINS  / (R_MAX - R_MIN));
    res.y = (th - tg.y) * (BEAMS / FOV_H);
    return res;
}

__global__ __launch_bounds__(1024) void ba_main(
    const float* __restrict__ target,       // float2 per edge
    const int*   __restrict__ src_idx,
    const int*   __restrict__ tgt_idx,
    const int*   __restrict__ patch_idx,
    float*       __restrict__ out,          // residual_proj (float2 per edge)
    int E)
{
    extern __shared__ char smem[];
    float4* s_q  = (float4*)smem;                          // 128 KB
    float*  s_tx = (float*)(smem + P_NUM * 16);            //  32 KB
    float*  s_ty = (float*)(smem + P_NUM * 20);            //  32 KB
    float*  s_tz = (float*)(smem + P_NUM * 24);            //  32 KB

    for (int i = threadIdx.x; i < P_NUM; i += blockDim.x) {
        s_q[i]  = g_quat[i];
        s_tx[i] = g_tx[i];
        s_ty[i] = g_ty[i];
        s_tz[i] = g_tz[i];
    }
    __syncthreads();

    SmemTables S{s_q, s_tx, s_ty, s_tz};

    const int pairs  = E >> 1;              // E even
    const int stride = gridDim.x * blockDim.x;
    for (int tid = blockIdx.x * blockDim.x + threadIdx.x; tid < pairs; tid += stride) {
        const int2   sp = __ldg(((const int2*)src_idx)   + tid);
        const int2   tp = __ldg(((const int2*)tgt_idx)   + tid);
        const int2   pp = __ldg(((const int2*)patch_idx) + tid);
        const float4 tg = __ldg(((const float4*)target)  + tid);

        const float2 r0 = project_one(S, pp.x, sp.x, tp.x, make_float2(tg.x, tg.y));
        const float2 r1 = project_one(S, pp.y, sp.y, tp.y, make_float2(tg.z, tg.w));

        ((float4*)out)[tid] = make_float4(r0.x, r0.y, r1.x, r1.y);
    }
}

extern "C" void kernel_launch(void* const* d_in, const int* in_sizes, int n_in,
                              void* d_out, int out_size)
{
    const float* poses        = (const float*)d_in[0];
    const float* init_poses   = (const float*)d_in[1];
    const float* patch_coords = (const float*)d_in[2];
    const float* elev         = (const float*)d_in[3];
    const float* init_elev    = (const float*)d_in[4];
    const float* target       = (const float*)d_in[5];
    const int*   src_idx      = (const int*)d_in[6];
    const int*   tgt_idx      = (const int*)d_in[7];
    const int*   patch_idx    = (const int*)d_in[8];
    float*       out          = (float*)d_out;

    const int E  = in_sizes[8];   // 4194304
    const int P7 = in_sizes[0];   // 57344
    const long long proj_elems = 2LL * E;

    // prepass
    {
        const int threads = 256;
        const int work = E >> 2;
        const int blocks = (work + threads - 1) / threads;
        prepass<<<blocks, threads>>>(
            poses, init_poses, patch_coords, elev, init_elev,
            out + proj_elems, out + proj_elems + P7, E, P7);
    }

    // main: 224 KB smem pose table, 1 block/SM
    {
        const int threads = 1024;
        const int smem_bytes = P_NUM * 28;  // 229376 bytes
        cudaFuncSetAttribute(ba_main, cudaFuncAttributeMaxDynamicSharedMemorySize, smem_bytes);
        const int blocks = 148;
        ba_main<<<blocks, threads, smem_bytes>>>(
            target, src_idx, tgt_idx, patch_idx, out, E);
    }
}